// round 14
// baseline (speedup 1.0000x reference)
#include <cuda_runtime.h>
#include <cuda_bf16.h>
#include <cstdint>

#define NMAX 100000
#define NPAD 100128
#define EMAX 1600000
#define FDIM 128
#define GMAX 64
#define CLS  10
#define SCAN_B 1024

// ---- scratch ----
__device__ float g_deg    [NMAX];
__device__ float g_dinv   [NMAX];
__device__ int   g_rcnt   [NMAX];
__device__ int   g_incl   [NMAX];
__device__ int   g_part   [256];
__device__ int   g_rowptr [NMAX + 1];
__device__ int   g_fill   [NMAX];
__device__ int2  g_csrent [EMAX];      // (src, w-as-int)
// fp32 feature buffers (prop I/O; X fp32 is the harness input)
__device__ float g_T1f[NPAD * FDIM];
__device__ float g_H1f[NPAD * FDIM];
__device__ float g_H2f[NPAD * FDIM];
// bf16 hi/lo planes (GEMM A-inputs), row = 512B, k-interleaved via posu32
__device__ uint32_t g_X [NPAD * 128];
__device__ uint32_t g_T1[NPAD * 128];
__device__ uint32_t g_Y [NPAD * 128];
__device__ uint32_t g_H1[NPAD * 128];
__device__ uint32_t g_H2[NPAD * 128];
__device__ float g_sums[GMAX * FDIM];
// combined weights: [layer][src(0:W0-W2, 1:W1, 2:2*W2)] 128 n-rows x 512B interleaved
__device__ uint32_t g_Wc[9 * 16384];

// byte offset (within a 512B row) of the u32 holding cols (c, c+1); lo plane at +8
__host__ __device__ __forceinline__ int posu32(int c) {
    int grp = c >> 4, pg = (c >> 1) & 7;
    return grp * 64 + (pg & 3) * 16 + (pg >> 2) * 4;
}
__device__ __forceinline__ void enc_pair(float2 v, uint32_t& h, uint32_t& l) {
    __nv_bfloat16 h0 = __float2bfloat16(v.x), h1 = __float2bfloat16(v.y);
    float l0 = v.x - __bfloat162float(h0), l1 = v.y - __bfloat162float(h1);
    union { __nv_bfloat162 b; uint32_t u; } t;
    t.b = __halves2bfloat162(h0, h1); h = t.u;
    t.b = __halves2bfloat162(__float2bfloat16(l0), __float2bfloat16(l1)); l = t.u;
}
// encode natural float4 (cols c4..c4+3) into a permuted plane row
__device__ __forceinline__ void enc_store(char* orow, int c4, float4 v) {
    uint32_t h0, l0, h1, l1;
    enc_pair(make_float2(v.x, v.y), h0, l0);
    enc_pair(make_float2(v.z, v.w), h1, l1);
    int p0 = posu32(c4), p1 = posu32(c4 + 2);
    *(uint32_t*)(orow + p0)     = h0;
    *(uint32_t*)(orow + p0 + 8) = l0;
    *(uint32_t*)(orow + p1)     = h1;
    *(uint32_t*)(orow + p1 + 8) = l1;
}

// ================= k1: degree + in-count =================
__global__ void degcnt_kernel(const int* __restrict__ src, const int* __restrict__ dst, int E) {
    int e = blockIdx.x * blockDim.x + threadIdx.x;
    if (e < E) {
        atomicAdd(&g_deg[src[e]], 1.0f);
        atomicAdd(&g_rcnt[dst[e]], 1);
    }
}
// ================= k2: per-block inclusive scans =================
__global__ void scan1_kernel(int n) {
    __shared__ int sm[SCAN_B];
    int i = blockIdx.x * SCAN_B + threadIdx.x;
    int v = (i < n) ? g_rcnt[i] : 0;
    sm[threadIdx.x] = v;
    __syncthreads();
    for (int off = 1; off < SCAN_B; off <<= 1) {
        int t = (threadIdx.x >= off) ? sm[threadIdx.x - off] : 0;
        __syncthreads();
        sm[threadIdx.x] += t;
        __syncthreads();
    }
    if (i < n) g_incl[i] = sm[threadIdx.x];
    if (threadIdx.x == SCAN_B - 1) g_part[blockIdx.x] = sm[threadIdx.x];
}
// ================= k3: partial-scan + rowptr + dinv =================
__global__ void scan23_kernel(int n, int nb) {
    __shared__ int pre[128];
    const int t = threadIdx.x;
    if (t < 32) {
        int run = 0;
#pragma unroll
        for (int j = 0; j < 4; ++j) {
            int idx = j * 32 + t;
            int v0 = (idx < nb) ? g_part[idx] : 0;
            int v = v0;
#pragma unroll
            for (int o = 1; o < 32; o <<= 1) {
                int u = __shfl_up_sync(0xffffffffu, v, o);
                if (t >= o) v += u;
            }
            pre[idx] = v - v0 + run;
            run += __shfl_sync(0xffffffffu, v, 31);
        }
    }
    __syncthreads();
    int i = blockIdx.x * blockDim.x + t;
    if (i < n) {
        g_rowptr[i + 1] = g_incl[i] + pre[i >> 10];
        float d = g_deg[i];
        g_dinv[i] = (d > 0.0f) ? rsqrtf(d) : 0.0f;
    }
    if (i == 0) g_rowptr[0] = 0;
}
// ================= k4: CSR fill =================
__global__ void fill_kernel(const int* __restrict__ src, const int* __restrict__ dst, int E) {
    int e = blockIdx.x * blockDim.x + threadIdx.x;
    if (e >= E) return;
    int d = dst[e], s = src[e];
    int p = g_rowptr[d] + atomicAdd(&g_fill[d], 1);
    float w = -g_dinv[s] * g_dinv[d];
    g_csrent[p] = make_int2(s, __float_as_int(w));
}
// ================= k5: X -> planes (permuted) =================
__global__ void xenc_kernel(const float4* __restrict__ X, int n) {
    int idx = blockIdx.x * blockDim.x + threadIdx.x;
    if (idx >= n * 32) return;
    int row = idx >> 5;
    int c4  = (idx & 31) << 2;
    float4 v = __ldg(&X[idx]);
    enc_store((char*)g_X + (size_t)row * 512, c4, v);
}

// ================= CSR propagation: fp32 gather, one warp per row ============
// WF32=1: write fp32 out + planes; WF32=0: planes only.
template <int WF32>
__global__ void __launch_bounds__(256) prop_csr_kernel(
    const float4* __restrict__ Xf, float4* __restrict__ Of, uint32_t* __restrict__ Opl, int n) {
    int gw = (blockIdx.x * blockDim.x + threadIdx.x) >> 5;
    if (gw >= n) return;
    int lane = threadIdx.x & 31;
    int p    = __ldg(&g_rowptr[gw]);
    int end  = __ldg(&g_rowptr[gw + 1]);
    float4 acc = make_float4(0.f, 0.f, 0.f, 0.f);
    for (; p + 7 < end; p += 8) {
        int2 e[8];
        float4 v[8];
#pragma unroll
        for (int i = 0; i < 8; ++i) e[i] = __ldg(&g_csrent[p + i]);
#pragma unroll
        for (int i = 0; i < 8; ++i) v[i] = __ldg(&Xf[(size_t)e[i].x * 32 + lane]);
#pragma unroll
        for (int i = 0; i < 8; ++i) {
            float w = __int_as_float(e[i].y);
            acc.x = fmaf(w, v[i].x, acc.x);
            acc.y = fmaf(w, v[i].y, acc.y);
            acc.z = fmaf(w, v[i].z, acc.z);
            acc.w = fmaf(w, v[i].w, acc.w);
        }
    }
    for (; p < end; ++p) {
        int2 e = __ldg(&g_csrent[p]);
        float w = __int_as_float(e.y);
        float4 v = __ldg(&Xf[(size_t)e.x * 32 + lane]);
        acc.x = fmaf(w, v.x, acc.x);
        acc.y = fmaf(w, v.y, acc.y);
        acc.z = fmaf(w, v.z, acc.z);
        acc.w = fmaf(w, v.w, acc.w);
    }
    if (WF32) Of[(size_t)gw * 32 + lane] = acc;
    enc_store((char*)Opl + (size_t)gw * 512, lane << 2, acc);
}

// ================= weight pre-conversion (combined Chebyshev weights) ============
__global__ void wcvt_kernel(const float* __restrict__ W1, const float* __restrict__ W2,
                            const float* __restrict__ W3, uint32_t* __restrict__ out) {
    int e = blockIdx.x * blockDim.x + threadIdx.x;
    if (e >= 9 * 8192) return;
    int L  = e / 24576;
    int r  = e % 24576;
    int s  = r >> 13;
    int rr = r & 8191;
    int p  = rr >> 7;
    int nn = rr & 127;
    const float* W = (L == 0) ? W1 : (L == 1) ? W2 : W3;
    int k = 2 * p;
    float v0, v1;
    if (s == 0) {
        v0 = W[k * 128 + nn]       - W[2 * 16384 + k * 128 + nn];
        v1 = W[(k + 1) * 128 + nn] - W[2 * 16384 + (k + 1) * 128 + nn];
    } else if (s == 1) {
        v0 = W[16384 + k * 128 + nn];
        v1 = W[16384 + (k + 1) * 128 + nn];
    } else {
        v0 = 2.0f * W[2 * 16384 + k * 128 + nn];
        v1 = 2.0f * W[2 * 16384 + (k + 1) * 128 + nn];
    }
    uint32_t h, l;
    enc_pair(make_float2(v0, v1), h, l);
    char* o = (char*)out + ((size_t)(L * 3 + s) * 128 + nn) * 512;
    int pos = posu32(k);
    *(uint32_t*)(o + pos)     = h;
    *(uint32_t*)(o + pos + 8) = l;
}

// ================= pipelined bf16 mma.sync GEMM =================
#define HP 320
#define SM_GEMM (4 * 128 * HP)

__device__ __forceinline__ uint32_t smem_u32(const void* p) {
    uint32_t a;
    asm("{ .reg .u64 t; cvta.to.shared.u64 t, %1; cvt.u32.u64 %0, t; }" : "=r"(a) : "l"(p));
    return a;
}
__device__ __forceinline__ void mma_bf16(float& d0, float& d1, float& d2, float& d3,
                                         uint32_t a0, uint32_t a1, uint32_t a2, uint32_t a3,
                                         uint32_t b0, uint32_t b1) {
    asm volatile("mma.sync.aligned.m16n8k16.row.col.f32.bf16.bf16.f32 "
                 "{%0,%1,%2,%3}, {%4,%5,%6,%7}, {%8,%9}, {%0,%1,%2,%3};"
                 : "+f"(d0), "+f"(d1), "+f"(d2), "+f"(d3)
                 : "r"(a0), "r"(a1), "r"(a2), "r"(a3), "r"(b0), "r"(b1));
}

// MODE 0: write H fp32 + planes (relu). MODE 2: red.global into g_sums[batch[row]].
template <int MODE>
__global__ void __launch_bounds__(256, 1) gemm_mma_kernel(
    const uint32_t* __restrict__ A0, const uint32_t* __restrict__ A1,
    const uint32_t* __restrict__ A2,
    const uint32_t* __restrict__ Wc, const float* __restrict__ bias,
    uint32_t* __restrict__ OUT, float* __restrict__ OUTF,
    const int* __restrict__ batch, int n)
{
    extern __shared__ __align__(16) char smem[];
    const int tid  = threadIdx.x;
    const int wid  = tid >> 5;
    const int lane = tid & 31;
    const int wm   = wid & 3;
    const int wn   = wid >> 2;
    const int row0 = blockIdx.x * 128;

    float acc[2][8][4];
#pragma unroll
    for (int i = 0; i < 2; ++i)
#pragma unroll
        for (int j = 0; j < 8; ++j)
#pragma unroll
            for (int c = 0; c < 4; ++c) acc[i][j][c] = 0.0f;

    const uint32_t smA[2] = { smem_u32(smem),                smem_u32(smem + 128 * HP) };
    const uint32_t smW[2] = { smem_u32(smem + 2 * 128 * HP), smem_u32(smem + 3 * 128 * HP) };
    const uint32_t* Asrc[3] = { A0, A1, A2 };

    auto stage = [&](int c) {
        int s = c >> 1, h = c & 1;
        const char* asrc = (const char*)Asrc[s] + (size_t)row0 * 512 + h * 256;
        const char* wsrc = (const char*)Wc + (size_t)s * 65536 + h * 256;
        uint32_t dA = smA[c & 1], dW = smW[c & 1];
#pragma unroll
        for (int i = 0; i < 8; ++i) {
            int q = i * 256 + tid;
            int r = q >> 4, g = q & 15;
            uint32_t od = (uint32_t)(r * HP + g * 16);
            size_t  so = (size_t)r * 512 + g * 16;
            asm volatile("cp.async.cg.shared.global [%0], [%1], 16;" :: "r"(dA + od), "l"(asrc + so));
            asm volatile("cp.async.cg.shared.global [%0], [%1], 16;" :: "r"(dW + od), "l"(wsrc + so));
        }
        asm volatile("cp.async.commit_group;" ::: "memory");
    };

    stage(0);
    stage(1);

#pragma unroll
    for (int c = 0; c < 6; ++c) {
        if (c < 5) asm volatile("cp.async.wait_group 1;" ::: "memory");
        else       asm volatile("cp.async.wait_group 0;" ::: "memory");
        __syncthreads();
        {
            const char* a0 = smem + (size_t)(c & 1) * 128 * HP
                           + (wm * 32 + (lane >> 2)) * HP + (lane & 3) * 16;
            const char* b0 = smem + (size_t)(2 + (c & 1)) * 128 * HP
                           + (wn * 64 + (lane >> 2)) * HP + (lane & 3) * 16;
#pragma unroll
            for (int g = 0; g < 4; ++g) {
                const int go = g * 64;
                uint4 va[4], vb[8];
#pragma unroll
                for (int r = 0; r < 4; ++r)
                    va[r] = *(const uint4*)(a0 + r * 8 * HP + go);
#pragma unroll
                for (int j = 0; j < 8; ++j)
                    vb[j] = *(const uint4*)(b0 + j * 8 * HP + go);
#pragma unroll
                for (int j = 0; j < 8; ++j) {
                    mma_bf16(acc[0][j][0], acc[0][j][1], acc[0][j][2], acc[0][j][3],
                             va[0].x, va[1].x, va[0].y, va[1].y, vb[j].x, vb[j].y);
                    mma_bf16(acc[1][j][0], acc[1][j][1], acc[1][j][2], acc[1][j][3],
                             va[2].x, va[3].x, va[2].y, va[3].y, vb[j].x, vb[j].y);
                    mma_bf16(acc[0][j][0], acc[0][j][1], acc[0][j][2], acc[0][j][3],
                             va[0].z, va[1].z, va[0].w, va[1].w, vb[j].x, vb[j].y);
                    mma_bf16(acc[1][j][0], acc[1][j][1], acc[1][j][2], acc[1][j][3],
                             va[2].z, va[3].z, va[2].w, va[3].w, vb[j].x, vb[j].y);
                    mma_bf16(acc[0][j][0], acc[0][j][1], acc[0][j][2], acc[0][j][3],
                             va[0].x, va[1].x, va[0].y, va[1].y, vb[j].z, vb[j].w);
                    mma_bf16(acc[1][j][0], acc[1][j][1], acc[1][j][2], acc[1][j][3],
                             va[2].x, va[3].x, va[2].y, va[3].y, vb[j].z, vb[j].w);
                }
            }
        }
        __syncthreads();
        if (c + 2 < 6) stage(c + 2);
    }

    // ---- epilogue ----
#pragma unroll
    for (int i = 0; i < 2; ++i) {
        int r0 = row0 + wm * 32 + i * 16 + (lane >> 2);
        int r1 = r0 + 8;
        int g0 = 0, g1 = 0;
        if (MODE == 2) {
            if (r0 < n) g0 = __ldg(&batch[r0]);
            if (r1 < n) g1 = __ldg(&batch[r1]);
        }
#pragma unroll
        for (int j = 0; j < 8; ++j) {
            int col = wn * 64 + j * 8 + (lane & 3) * 2;
            float2 bv = __ldg((const float2*)&bias[col]);
            float2 o0 = make_float2(acc[i][j][0] + bv.x, acc[i][j][1] + bv.y);
            float2 o1 = make_float2(acc[i][j][2] + bv.x, acc[i][j][3] + bv.y);
            if (MODE == 0) {
                o0.x = fmaxf(o0.x, 0.f); o0.y = fmaxf(o0.y, 0.f);
                o1.x = fmaxf(o1.x, 0.f); o1.y = fmaxf(o1.y, 0.f);
                int pos = posu32(col);
                uint32_t h, l;
                if (r0 < n) {
                    enc_pair(o0, h, l);
                    char* orow = (char*)OUT + (size_t)r0 * 512;
                    *(uint32_t*)(orow + pos)     = h;
                    *(uint32_t*)(orow + pos + 8) = l;
                    *(float2*)&OUTF[(size_t)r0 * FDIM + col] = o0;
                }
                if (r1 < n) {
                    enc_pair(o1, h, l);
                    char* orow = (char*)OUT + (size_t)r1 * 512;
                    *(uint32_t*)(orow + pos)     = h;
                    *(uint32_t*)(orow + pos + 8) = l;
                    *(float2*)&OUTF[(size_t)r1 * FDIM + col] = o1;
                }
            } else {
                if (r0 < n) {
                    float* p = &g_sums[g0 * FDIM + col];
                    asm volatile("red.global.add.v2.f32 [%0], {%1,%2};"
                                 :: "l"(p), "f"(o0.x), "f"(o0.y) : "memory");
                }
                if (r1 < n) {
                    float* p = &g_sums[g1 * FDIM + col];
                    asm volatile("red.global.add.v2.f32 [%0], {%1,%2};"
                                 :: "l"(p), "f"(o1.x), "f"(o1.y) : "memory");
                }
            }
        }
    }
}

// ================= classifier =================
__global__ void final_kernel(const int* __restrict__ batch, int n,
                             const float* __restrict__ Wl, const float* __restrict__ bl,
                             float* __restrict__ out, int ngraphs) {
    int tid = blockIdx.x * blockDim.x + threadIdx.x;
    if (tid >= ngraphs * CLS) return;
    int g = tid / CLS;
    int c = tid % CLS;
    int lo = 0, hi = n;
    while (lo < hi) { int m = (lo + hi) >> 1; if (__ldg(&batch[m]) < g) lo = m + 1; else hi = m; }
    int start = lo;
    lo = start; hi = n;
    while (lo < hi) { int m = (lo + hi) >> 1; if (__ldg(&batch[m]) < g + 1) lo = m + 1; else hi = m; }
    float cnt = (float)(lo - start);
    float s = 0.0f;
    const float* sp = &g_sums[g * FDIM];
#pragma unroll 16
    for (int d = 0; d < FDIM; ++d) s = fmaf(sp[d], Wl[d * CLS + c], s);
    out[g * CLS + c] = s / fmaxf(cnt, 1.0f) + bl[c];
}

// ---------------------------------------------------------------
extern "C" void kernel_launch(void* const* d_in, const int* in_sizes, int n_in,
                              void* d_out, int out_size) {
    const float* x   = (const float*)d_in[0];
    const int*   ei  = (const int*)  d_in[1];
    const int*   bat = (const int*)  d_in[2];
    const float* W1  = (const float*)d_in[3];
    const float* b1  = (const float*)d_in[4];
    const float* W2  = (const float*)d_in[5];
    const float* b2  = (const float*)d_in[6];
    const float* W3  = (const float*)d_in[7];
    const float* b3  = (const float*)d_in[8];
    const float* Wl  = (const float*)d_in[9];
    const float* bl  = (const float*)d_in[10];
    float* out = (float*)d_out;

    const int n = in_sizes[0] / FDIM;
    const int E = in_sizes[1] / 2;
    const int G = out_size / CLS;
    const int* src = ei;
    const int* dst = ei + E;
    const int ntiles = (n + 127) / 128;

    float *deg, *sums, *T1f, *H1f, *H2f;
    int *rcnt, *fill;
    uint32_t *X, *T1, *Y, *H1, *H2, *Wc;
    cudaGetSymbolAddress((void**)&deg,  g_deg);
    cudaGetSymbolAddress((void**)&rcnt, g_rcnt);
    cudaGetSymbolAddress((void**)&fill, g_fill);
    cudaGetSymbolAddress((void**)&T1f, g_T1f);
    cudaGetSymbolAddress((void**)&H1f, g_H1f);
    cudaGetSymbolAddress((void**)&H2f, g_H2f);
    cudaGetSymbolAddress((void**)&X,  g_X);
    cudaGetSymbolAddress((void**)&T1, g_T1);
    cudaGetSymbolAddress((void**)&Y,  g_Y);
    cudaGetSymbolAddress((void**)&H1, g_H1);
    cudaGetSymbolAddress((void**)&H2, g_H2);
    cudaGetSymbolAddress((void**)&sums, g_sums);
    cudaGetSymbolAddress((void**)&Wc,   g_Wc);

    cudaFuncSetAttribute(gemm_mma_kernel<0>, cudaFuncAttributeMaxDynamicSharedMemorySize, SM_GEMM);
    cudaFuncSetAttribute(gemm_mma_kernel<2>, cudaFuncAttributeMaxDynamicSharedMemorySize, SM_GEMM);

    const int TB = 256;

    cudaMemsetAsync(deg,  0, (size_t)n * sizeof(float));
    cudaMemsetAsync(rcnt, 0, (size_t)n * sizeof(int));
    cudaMemsetAsync(fill, 0, (size_t)n * sizeof(int));
    cudaMemsetAsync(sums, 0, (size_t)G * FDIM * sizeof(float));

    // prepass
    degcnt_kernel<<<(E + TB - 1) / TB, TB>>>(src, dst, E);
    const int nb = (n + SCAN_B - 1) / SCAN_B;
    scan1_kernel<<<nb, SCAN_B>>>(n);
    scan23_kernel<<<(n + TB - 1) / TB, TB>>>(n, nb);
    fill_kernel<<<(E + TB - 1) / TB, TB>>>(src, dst, E);
    xenc_kernel<<<(n * 32 + TB - 1) / TB, TB>>>((const float4*)x, n);
    wcvt_kernel<<<(9 * 8192 + TB - 1) / TB, TB>>>(W1, W2, W3, Wc);

    const int propBlocks = (n * 32 + TB - 1) / TB;

    // layer 1: gather x (fp32 input), then T1f
    prop_csr_kernel<1><<<propBlocks, TB>>>((const float4*)x, (float4*)T1f, T1, n);
    prop_csr_kernel<0><<<propBlocks, TB>>>((const float4*)T1f, nullptr, Y, n);
    gemm_mma_kernel<0><<<ntiles, 256, SM_GEMM>>>(X, T1, Y, Wc, b1, H1, H1f, nullptr, n);
    // layer 2
    prop_csr_kernel<1><<<propBlocks, TB>>>((const float4*)H1f, (float4*)T1f, T1, n);
    prop_csr_kernel<0><<<propBlocks, TB>>>((const float4*)T1f, nullptr, Y, n);
    gemm_mma_kernel<0><<<ntiles, 256, SM_GEMM>>>(H1, T1, Y, Wc + (size_t)3 * 16384, b2, H2, H2f, nullptr, n);
    // layer 3 (pool fused)
    prop_csr_kernel<1><<<propBlocks, TB>>>((const float4*)H2f, (float4*)T1f, T1, n);
    prop_csr_kernel<0><<<propBlocks, TB>>>((const float4*)T1f, nullptr, Y, n);
    gemm_mma_kernel<2><<<ntiles, 256, SM_GEMM>>>(H2, T1, Y, Wc + (size_t)6 * 16384, b3, nullptr, nullptr, bat, n);

    // classifier
    final_kernel<<<(G * CLS + TB - 1) / TB, TB>>>(bat, n, Wl, bl, out, G);
}